// round 16
// baseline (speedup 1.0000x reference)
#include <cuda_runtime.h>
#include <cuda_fp16.h>
#include <cstdint>
#include <math.h>

// Problem: B=4,S=2048 -> T=8192 tokens, H=1024, E=8, top-2.
#define Tt  8192
#define Hh  1024
#define HD2 2048
#define NE  8

// GEMM tiling: CTA 128x128 with 128 threads = 4 warps (2m x 2n) of 64x64.
// K-chunk = 64 halfs = 128 B/row; 4 k16 mma steps per chunk.
#define TM 128
#define TN 128
#define TK 64                           // K halfs per stage chunk
#define ROWPB 144                       // padded smem row: 128B data + 16B pad

#define SA_BYTES  (TM * ROWPB)          // 18432
#define STAGE     (2 * SA_BYTES)        // 36864 (A + B)
#define NSTAGE    3
#define SMEM_BYTES (NSTAGE * STAGE)     // 110592 (x2 CTAs = 221184 <= 228KB)

// ---------------- device scratch (alloc-free rule) ----------------
__device__ int    g_cnt[NE];
__device__ int    g_off[NE];
__device__ int    g_tok[NE * Tt];
__device__ int4   g_info[Tt];
__device__ float2 g_wts[Tt];
__device__ __half g_xh [(size_t)Tt * Hh];        // fp16 x        (16MB)
__device__ __half g_w1h[(size_t)NE * HD2 * Hh];  // fp16 w1       (32MB)
__device__ __half g_w2h[(size_t)NE * Hh * HD2];  // fp16 w2       (32MB)
__device__ __half g_hbuf[(size_t)2 * Tt * HD2];  // fp16 gelu(x@w1^T) (64MB)
__device__ float  g_ybuf[(size_t)2 * Tt * Hh];   // y per slot    (64MB)

// ---------------- helpers ----------------
__device__ __forceinline__ uint32_t smem_u32(const void* p) {
    uint32_t a;
    asm("{ .reg .u64 t; cvta.to.shared.u64 t, %1; cvt.u32.u64 %0, t; }" : "=r"(a) : "l"(p));
    return a;
}
__device__ __forceinline__ float gelu_f(float v) {
    return 0.5f * v * (1.0f + erff(v * 0.70710678118654752f));
}
#define CPA(dst, src, n) \
    asm volatile("cp.async.cg.shared.global [%0], [%1], 16, %2;" \
                 :: "r"(dst), "l"(src), "r"(n) : "memory")
#define CPC() asm volatile("cp.async.commit_group;" ::: "memory")
#define CPW(N) asm volatile("cp.async.wait_group %0;" :: "n"(N) : "memory")

// ldmatrix x4: four m8n8 16B-row tiles; lane l supplies row (l&7) of tile (l>>3).
#define LDSM4(r0, r1, r2, r3, addr) \
    asm volatile("ldmatrix.sync.aligned.m8n8.x4.shared.b16 {%0,%1,%2,%3}, [%4];" \
        : "=r"(r0), "=r"(r1), "=r"(r2), "=r"(r3) : "r"(addr))

// m16n8k16 fp16 mma, fp32 accumulate, in-place C.
__device__ __forceinline__ void mma16(float* c, const uint32_t* a, uint32_t b0, uint32_t b1) {
    asm volatile("mma.sync.aligned.m16n8k16.row.col.f32.f16.f16.f32 "
        "{%0,%1,%2,%3}, {%4,%5,%6,%7}, {%8,%9}, {%0,%1,%2,%3};"
        : "+f"(c[0]), "+f"(c[1]), "+f"(c[2]), "+f"(c[3])
        : "r"(a[0]), "r"(a[1]), "r"(a[2]), "r"(a[3]), "r"(b0), "r"(b1));
}

// ---------------------------------------------------------------------------
// Prepass: fp32 -> fp16 for x, w1, w2 in ONE launch (gemm1 stays in ncu slot 4).
// ---------------------------------------------------------------------------
#define N4X (Tt * Hh / 4)
#define N4W (NE * HD2 * Hh / 4)
__global__ __launch_bounds__(256) void cvt_all_kernel(const float4* __restrict__ x,
                                                      const float4* __restrict__ w1,
                                                      const float4* __restrict__ w2) {
    int i = blockIdx.x * 256 + threadIdx.x;
    const float4* s; __half2* d;
    if (i < N4X)                { s = x  + i;               d = (__half2*)g_xh  + 2 * i; }
    else if (i < N4X + N4W)     { s = w1 + (i - N4X);       d = (__half2*)g_w1h + 2 * (i - N4X); }
    else if (i < N4X + 2 * N4W) { s = w2 + (i - N4X - N4W); d = (__half2*)g_w2h + 2 * (i - N4X - N4W); }
    else return;
    float4 v = *s;
    d[0] = __floats2half2_rn(v.x, v.y);
    d[1] = __floats2half2_rn(v.z, v.w);
}

// ---------------------------------------------------------------------------
// Router: one warp per token; logits, top-2, softmax, expert lists + meta.
// ---------------------------------------------------------------------------
__global__ __launch_bounds__(256) void router_kernel(const float* __restrict__ x,
                                                     const float* __restrict__ rw) {
    __shared__ float s_rw[NE * Hh];
    for (int i = threadIdx.x; i < NE * Hh; i += 256) s_rw[i] = rw[i];
    __syncthreads();

    int warp = threadIdx.x >> 5, lane = threadIdx.x & 31;
    int t = blockIdx.x * 8 + warp;

    float xv[32];
    const float* xr = x + (size_t)t * Hh;
#pragma unroll
    for (int i = 0; i < 32; i++) xv[i] = xr[i * 32 + lane];

    float logit[NE];
#pragma unroll
    for (int e = 0; e < NE; e++) {
        float p = 0.f;
        const float* w = s_rw + e * Hh;
#pragma unroll
        for (int i = 0; i < 32; i++) p += xv[i] * w[i * 32 + lane];
#pragma unroll
        for (int o = 16; o > 0; o >>= 1) p += __shfl_xor_sync(0xffffffffu, p, o);
        logit[e] = p;
    }

    if (lane == 0) {
        int e0 = 0; float v0 = logit[0];
#pragma unroll
        for (int e = 1; e < NE; e++) if (logit[e] > v0) { v0 = logit[e]; e0 = e; }
        int e1 = -1; float v1 = -3.4e38f;
#pragma unroll
        for (int e = 0; e < NE; e++) if (e != e0 && logit[e] > v1) { v1 = logit[e]; e1 = e; }
        float w0 = 1.f / (1.f + expf(v1 - v0));
        float w1v = 1.f - w0;
        int p0 = atomicAdd(&g_cnt[e0], 1);
        g_tok[e0 * Tt + p0] = t;
        int p1 = atomicAdd(&g_cnt[e1], 1);
        g_tok[e1 * Tt + p1] = t;
        g_info[t] = make_int4(e0, p0, e1, p1);
        g_wts[t] = make_float2(w0, w1v);
    }
}

__global__ void offsets_kernel() {
    if (threadIdx.x == 0) {
        int s = 0;
#pragma unroll
        for (int e = 0; e < NE; e++) { g_off[e] = s; s += g_cnt[e]; }
    }
}

// ---------------------------------------------------------------------------
// Grouped FP16 GEMM: D[128,128] = A @ B^T, A gathered. 128-thread CTA,
// 4 warps (2x2) of 64x64 tiles: halves smem fragment bytes per MAC vs 32x64
// (crossbar 1560c < tensor floor 2048c). 2 CTAs/SM (reg cap 256/thread).
// m16n8k16 + ldmatrix.x4, 3-stage cp.async.
// FIRST: A = g_xh by g_tok (K=1024); out = fp16(gelu(.)) -> g_hbuf
// else : A = g_hbuf by slot (K=2048); out = fp32 -> g_ybuf
// ---------------------------------------------------------------------------
template<int KTOT, bool FIRST>
__global__ __launch_bounds__(128, 2) void moe_gemm_kernel(const __half* __restrict__ Abase,
                                                          const __half* __restrict__ Wb,
                                                          __half* __restrict__ OutH,
                                                          float* __restrict__ OutF) {
    int e = blockIdx.z;
    int cnt = g_cnt[e];
    int m0 = blockIdx.x * TM;
    if (m0 >= cnt) return;
    int n0 = blockIdx.y * TN;
    const int LDO = FIRST ? HD2 : Hh;

    extern __shared__ char smem[];
    uint32_t sbase = smem_u32(smem);
    int tid = threadIdx.x;
    int wid = tid >> 5, lane = tid & 31;
    int wm = wid & 1;              // 2 M blocks of 64
    int wn = wid >> 1;             // 2 N blocks of 64
    int lq = lane >> 2;            // quad row 0..7
    int lr = lane & 3;             // 0..3

    // cp.async slots: A/B each 128 rows x 8 x16B = 1024 slots -> 8/thread each.
    int frow = tid >> 3;                    // 0..15
    int fc16 = tid & 7;                     // 16B col 0..7
    const __half* asrc[8]; uint32_t anv[8];
#pragma unroll
    for (int i = 0; i < 8; i++) {
        int r = frow + i * 16;              // 0..127
        bool av = (m0 + r) < cnt;
        anv[i] = av ? 16u : 0u;
        int grow;
        if (FIRST) grow = av ? g_tok[e * Tt + m0 + r] : 0;
        else       grow = g_off[e] + m0 + (av ? r : 0);
        asrc[i] = Abase + (size_t)grow * KTOT + fc16 * 8;
    }
    const __half* bsrc0 = Wb + (size_t)e * (size_t)KTOT * (FIRST ? HD2 : Hh)
                        + (size_t)(n0 + frow) * KTOT + fc16 * 8;
    uint32_t adst0 = sbase + frow * ROWPB + fc16 * 16;             // + i*16*ROWPB
    uint32_t bdst0 = adst0 + SA_BYTES;

    // ldmatrix base addresses (add buf*STAGE + ks*32 + tile offs in loop).
    // A im tile (rows wm*64+im*16): t0 m0-7@+0B t1 m8-15@+0B t2 m0-7@+16B t3 m8-15@+16B
    uint32_t aAdr = sbase + (uint32_t)((wm * 64 + ((lane >> 3) & 1) * 8 + (lane & 7)) * ROWPB
                                       + (lane >> 4) * 16);
    // B jp tile (rows wn*64+jp*16): t0 n0-7@+0B t1 n0-7@+16B t2 n8-15@+0B t3 n8-15@+16B
    uint32_t bAdr = sbase + SA_BYTES
                  + (uint32_t)((wn * 64 + (lane >> 4) * 8 + (lane & 7)) * ROWPB
                               + ((lane >> 3) & 1) * 16);

    float cf[4][8][4];
#pragma unroll
    for (int i = 0; i < 4; i++)
#pragma unroll
        for (int j = 0; j < 8; j++)
#pragma unroll
            for (int k = 0; k < 4; k++) cf[i][j][k] = 0.f;

    const int S = KTOT / TK;
#pragma unroll
    for (int s = 0; s < 2; s++) {
#pragma unroll
        for (int i = 0; i < 8; i++)
            CPA(adst0 + s * STAGE + i * (16 * ROWPB), asrc[i] + s * TK, anv[i]);
#pragma unroll
        for (int i = 0; i < 8; i++)
            CPA(bdst0 + s * STAGE + i * (16 * ROWPB), bsrc0 + (size_t)i * 16 * KTOT + s * TK, 16u);
        CPC();
    }

    int buf = 0;
    for (int s = 0; s < S; s++) {
        if (s + 1 < S) { CPW(1); } else { CPW(0); }
        __syncthreads();
        if (s + 2 < S) {
            int b2 = buf + 2; if (b2 >= NSTAGE) b2 -= NSTAGE;
            int k0 = (s + 2) * TK;
#pragma unroll
            for (int i = 0; i < 8; i++)
                CPA(adst0 + b2 * STAGE + i * (16 * ROWPB), asrc[i] + k0, anv[i]);
#pragma unroll
            for (int i = 0; i < 8; i++)
                CPA(bdst0 + b2 * STAGE + i * (16 * ROWPB), bsrc0 + (size_t)i * 16 * KTOT + k0, 16u);
            CPC();
        }
        uint32_t bufoff = (uint32_t)(buf * STAGE);
#pragma unroll
        for (int ks = 0; ks < 4; ks++) {       // 4 x k16 covers TK=64 halfs
            uint32_t koff = bufoff + ks * 32;  // 16 halfs = 32B per k-step
            uint32_t a[4][4];
#pragma unroll
            for (int im = 0; im < 4; im++)
                LDSM4(a[im][0], a[im][1], a[im][2], a[im][3],
                      aAdr + koff + im * (16 * ROWPB));
#pragma unroll
            for (int jp = 0; jp < 4; jp++) {
                uint32_t b0, b1, b2, b3;   // (b0,b1)=jn 2jp, (b2,b3)=jn 2jp+1
                LDSM4(b0, b1, b2, b3, bAdr + koff + jp * (16 * ROWPB));
#pragma unroll
                for (int im = 0; im < 4; im++) {
                    mma16(cf[im][2 * jp],     a[im], b0, b1);
                    mma16(cf[im][2 * jp + 1], a[im], b2, b3);
                }
            }
        }
        if (++buf == NSTAGE) buf = 0;
    }

    // ---------------- epilogue ----------------
    int base_slot = g_off[e] + m0;
    int colb = n0 + wn * 64 + 2 * lr;
#pragma unroll
    for (int im = 0; im < 4; im++) {
#pragma unroll
        for (int h = 0; h < 2; h++) {
            int r = wm * 64 + im * 16 + lq + h * 8;
            if (m0 + r >= cnt) continue;
            if (FIRST) {
                __half* orow = OutH + (size_t)(base_slot + r) * LDO + colb;
#pragma unroll
                for (int jn = 0; jn < 8; jn++) {
                    float v0 = gelu_f(cf[im][jn][2 * h]);
                    float v1 = gelu_f(cf[im][jn][2 * h + 1]);
                    *(__half2*)(orow + jn * 8) = __floats2half2_rn(v0, v1);
                }
            } else {
                float* orow = OutF + (size_t)(base_slot + r) * LDO + colb;
#pragma unroll
                for (int jn = 0; jn < 8; jn++)
                    *(float2*)(orow + jn * 8) = make_float2(cf[im][jn][2 * h],
                                                            cf[im][jn][2 * h + 1]);
            }
        }
    }
}

// ---------------------------------------------------------------------------
// Combine: out[t] = w0 * y[slot0] + w1 * y[slot1]
// ---------------------------------------------------------------------------
__global__ __launch_bounds__(256) void combine_kernel(float* __restrict__ out) {
    int t = blockIdx.x;
    int c = threadIdx.x;
    int4 mi = g_info[t];
    float2 gw = g_wts[t];
    size_t s0 = (size_t)(g_off[mi.x] + mi.y) * Hh + c * 4;
    size_t s1 = (size_t)(g_off[mi.z] + mi.w) * Hh + c * 4;
    float4 a = *(const float4*)(g_ybuf + s0);
    float4 b = *(const float4*)(g_ybuf + s1);
    float4 o;
    o.x = gw.x * a.x + gw.y * b.x;
    o.y = gw.x * a.y + gw.y * b.y;
    o.z = gw.x * a.z + gw.y * b.z;
    o.w = gw.x * a.w + gw.y * b.w;
    *(float4*)(out + (size_t)t * Hh + c * 4) = o;
}

// ---------------------------------------------------------------------------
extern "C" void kernel_launch(void* const* d_in, const int* in_sizes, int n_in,
                              void* d_out, int out_size) {
    const float* x  = (const float*)d_in[0];
    const float* rw = (const float*)d_in[1];
    const float* w1 = (const float*)d_in[2];
    const float* w2 = (const float*)d_in[3];
    float* out = (float*)d_out;

    void* cntp = nullptr; cudaGetSymbolAddress(&cntp, g_cnt);
    cudaMemsetAsync(cntp, 0, sizeof(int) * NE);

    void *xh, *w1h, *w2h, *hb, *yb;
    cudaGetSymbolAddress(&xh,  g_xh);
    cudaGetSymbolAddress(&w1h, g_w1h);
    cudaGetSymbolAddress(&w2h, g_w2h);
    cudaGetSymbolAddress(&hb,  g_hbuf);
    cudaGetSymbolAddress(&yb,  g_ybuf);

    // Launch order: memset(0) router(1) offsets(2) cvt(3) gemm1(4) gemm2(5) combine(6)
    // -> ncu -s 5 -c 1 captures gemm1.
    router_kernel<<<Tt / 8, 256>>>(x, rw);
    offsets_kernel<<<1, 32>>>();
    cvt_all_kernel<<<(N4X + 2 * N4W + 255) / 256, 256>>>((const float4*)x,
                                                         (const float4*)w1,
                                                         (const float4*)w2);

    cudaFuncSetAttribute(moe_gemm_kernel<Hh, true>,
                         cudaFuncAttributeMaxDynamicSharedMemorySize, SMEM_BYTES);
    cudaFuncSetAttribute(moe_gemm_kernel<HD2, false>,
                         cudaFuncAttributeMaxDynamicSharedMemorySize, SMEM_BYTES);

    dim3 g1(Tt / TM, HD2 / TN, NE);   // (64, 16, 8): GEMM1  N=2048, K=1024
    dim3 g2(Tt / TM, Hh  / TN, NE);   // (64,  8, 8): GEMM2  N=1024, K=2048
    moe_gemm_kernel<Hh,  true ><<<g1, 128, SMEM_BYTES>>>((const __half*)xh,
                                                         (const __half*)w1h,
                                                         (__half*)hb, nullptr);
    moe_gemm_kernel<HD2, false><<<g2, 128, SMEM_BYTES>>>((const __half*)hb,
                                                         (const __half*)w2h,
                                                         nullptr, (float*)yb);

    combine_kernel<<<Tt, 256>>>(out);
}

// round 17
// speedup vs baseline: 1.1121x; 1.1121x over previous
#include <cuda_runtime.h>
#include <cuda_fp16.h>
#include <cstdint>
#include <math.h>

// Problem: B=4,S=2048 -> T=8192 tokens, H=1024, E=8, top-2.
#define Tt  8192
#define Hh  1024
#define HD2 2048
#define NE  8

// GEMM tiling: CTA 128x128, 256 threads = 8 warps (4m x 2n) of 32x64.
// K-chunk = 64 halfs = 128 B/row; 4 k16 mma steps per chunk.
#define TM 128
#define TN 128
#define TK 64                           // K halfs per stage chunk
#define ROWPB 144                       // padded smem row: 128B data + 16B pad

#define SA_BYTES  (TM * ROWPB)          // 18432
#define STAGE     (2 * SA_BYTES)        // 36864 (A + B)
#define NSTAGE    3
#define SMEM_BYTES (NSTAGE * STAGE)     // 110592 (x2 CTAs = 221184 <= 228KB)

// ---------------- device scratch (alloc-free rule) ----------------
__device__ int    g_cnt[NE];
__device__ int    g_off[NE];
__device__ int    g_tok[NE * Tt];
__device__ int4   g_info[Tt];
__device__ float2 g_wts[Tt];
__device__ __half g_xh [(size_t)Tt * Hh];        // fp16 x        (16MB)
__device__ __half g_w1h[(size_t)NE * HD2 * Hh];  // fp16 w1       (32MB)
__device__ __half g_w2h[(size_t)NE * Hh * HD2];  // fp16 w2       (32MB)
__device__ __half g_hbuf[(size_t)2 * Tt * HD2];  // fp16 gelu(x@w1^T) (64MB)
__device__ float  g_ybuf[(size_t)2 * Tt * Hh];   // y per slot    (64MB)

// ---------------- helpers ----------------
__device__ __forceinline__ uint32_t smem_u32(const void* p) {
    uint32_t a;
    asm("{ .reg .u64 t; cvta.to.shared.u64 t, %1; cvt.u32.u64 %0, t; }" : "=r"(a) : "l"(p));
    return a;
}
__device__ __forceinline__ float gelu_f(float v) {
    return 0.5f * v * (1.0f + erff(v * 0.70710678118654752f));
}
#define CPA(dst, src, n) \
    asm volatile("cp.async.cg.shared.global [%0], [%1], 16, %2;" \
                 :: "r"(dst), "l"(src), "r"(n) : "memory")
#define CPC() asm volatile("cp.async.commit_group;" ::: "memory")
#define CPW(N) asm volatile("cp.async.wait_group %0;" :: "n"(N) : "memory")

// ldmatrix x4: four m8n8 16B-row tiles; lane l supplies row (l&7) of tile (l>>3).
#define LDSM4(r0, r1, r2, r3, addr) \
    asm volatile("ldmatrix.sync.aligned.m8n8.x4.shared.b16 {%0,%1,%2,%3}, [%4];" \
        : "=r"(r0), "=r"(r1), "=r"(r2), "=r"(r3) : "r"(addr))

// m16n8k16 fp16 mma, fp32 accumulate, in-place C.
__device__ __forceinline__ void mma16(float* c, const uint32_t* a, uint32_t b0, uint32_t b1) {
    asm volatile("mma.sync.aligned.m16n8k16.row.col.f32.f16.f16.f32 "
        "{%0,%1,%2,%3}, {%4,%5,%6,%7}, {%8,%9}, {%0,%1,%2,%3};"
        : "+f"(c[0]), "+f"(c[1]), "+f"(c[2]), "+f"(c[3])
        : "r"(a[0]), "r"(a[1]), "r"(a[2]), "r"(a[3]), "r"(b0), "r"(b1));
}

// ---------------------------------------------------------------------------
// Prepass: fp32 -> fp16 for x, w1, w2 in ONE launch (gemm1 stays in ncu slot 4).
// ---------------------------------------------------------------------------
#define N4X (Tt * Hh / 4)
#define N4W (NE * HD2 * Hh / 4)
__global__ __launch_bounds__(256) void cvt_all_kernel(const float4* __restrict__ x,
                                                      const float4* __restrict__ w1,
                                                      const float4* __restrict__ w2) {
    int i = blockIdx.x * 256 + threadIdx.x;
    const float4* s; __half2* d;
    if (i < N4X)                { s = x  + i;               d = (__half2*)g_xh  + 2 * i; }
    else if (i < N4X + N4W)     { s = w1 + (i - N4X);       d = (__half2*)g_w1h + 2 * (i - N4X); }
    else if (i < N4X + 2 * N4W) { s = w2 + (i - N4X - N4W); d = (__half2*)g_w2h + 2 * (i - N4X - N4W); }
    else return;
    float4 v = *s;
    d[0] = __floats2half2_rn(v.x, v.y);
    d[1] = __floats2half2_rn(v.z, v.w);
}

// ---------------------------------------------------------------------------
// Router: one warp per token; logits, top-2, softmax, expert lists + meta.
// ---------------------------------------------------------------------------
__global__ __launch_bounds__(256) void router_kernel(const float* __restrict__ x,
                                                     const float* __restrict__ rw) {
    __shared__ float s_rw[NE * Hh];
    for (int i = threadIdx.x; i < NE * Hh; i += 256) s_rw[i] = rw[i];
    __syncthreads();

    int warp = threadIdx.x >> 5, lane = threadIdx.x & 31;
    int t = blockIdx.x * 8 + warp;

    float xv[32];
    const float* xr = x + (size_t)t * Hh;
#pragma unroll
    for (int i = 0; i < 32; i++) xv[i] = xr[i * 32 + lane];

    float logit[NE];
#pragma unroll
    for (int e = 0; e < NE; e++) {
        float p = 0.f;
        const float* w = s_rw + e * Hh;
#pragma unroll
        for (int i = 0; i < 32; i++) p += xv[i] * w[i * 32 + lane];
#pragma unroll
        for (int o = 16; o > 0; o >>= 1) p += __shfl_xor_sync(0xffffffffu, p, o);
        logit[e] = p;
    }

    if (lane == 0) {
        int e0 = 0; float v0 = logit[0];
#pragma unroll
        for (int e = 1; e < NE; e++) if (logit[e] > v0) { v0 = logit[e]; e0 = e; }
        int e1 = -1; float v1 = -3.4e38f;
#pragma unroll
        for (int e = 0; e < NE; e++) if (e != e0 && logit[e] > v1) { v1 = logit[e]; e1 = e; }
        float w0 = 1.f / (1.f + expf(v1 - v0));
        float w1v = 1.f - w0;
        int p0 = atomicAdd(&g_cnt[e0], 1);
        g_tok[e0 * Tt + p0] = t;
        int p1 = atomicAdd(&g_cnt[e1], 1);
        g_tok[e1 * Tt + p1] = t;
        g_info[t] = make_int4(e0, p0, e1, p1);
        g_wts[t] = make_float2(w0, w1v);
    }
}

__global__ void offsets_kernel() {
    if (threadIdx.x == 0) {
        int s = 0;
#pragma unroll
        for (int e = 0; e < NE; e++) { g_off[e] = s; s += g_cnt[e]; }
    }
}

// ---------------------------------------------------------------------------
// Grouped FP16 GEMM: D[128,128] = A @ B^T, A gathered. R13 geometry
// (8 warps 4x2 of 32x64, TK=64, 3-stage cp.async, 2 CTAs/SM) with:
//  - consolidated address regs (single bases + immediate offsets)
//  - ks-loop software pipeline: B fragments double-buffered, LDSM(jp+1)
//    issued before mma(jp) so LDS latency hides under the mma chain.
// FIRST: A = g_xh by g_tok (K=1024); out = fp16(gelu(.)) -> g_hbuf
// else : A = g_hbuf by slot (K=2048); out = fp32 -> g_ybuf
// ---------------------------------------------------------------------------
template<int KTOT, bool FIRST>
__global__ __launch_bounds__(256, 2) void moe_gemm_kernel(const __half* __restrict__ Abase,
                                                          const __half* __restrict__ Wb,
                                                          __half* __restrict__ OutH,
                                                          float* __restrict__ OutF) {
    int e = blockIdx.z;
    int cnt = g_cnt[e];
    int m0 = blockIdx.x * TM;
    if (m0 >= cnt) return;
    int n0 = blockIdx.y * TN;
    const int LDO = FIRST ? HD2 : Hh;

    extern __shared__ char smem[];
    uint32_t sbase = smem_u32(smem);
    int tid = threadIdx.x;
    int wid = tid >> 5, lane = tid & 31;
    int wm = wid & 3, wn = wid >> 2;
    int lq = lane >> 2;            // quad row 0..7
    int lr = lane & 3;             // 0..3

    // ---- fill descriptors (single bases + immediate offsets) ----
    // A/B each: 128 rows x 8 x16B = 1024 slots -> 4/thread (row = frow + i*32).
    int frow = tid >> 3;                    // 0..31
    int fc16 = tid & 7;                     // 16B col 0..7
    const __half* asrc[4]; uint32_t anv[4];
#pragma unroll
    for (int i = 0; i < 4; i++) {
        int r = frow + i * 32;              // 0..127
        bool av = (m0 + r) < cnt;
        anv[i] = av ? 16u : 0u;
        int grow;
        if (FIRST) grow = av ? g_tok[e * Tt + m0 + r] : 0;
        else       grow = g_off[e] + m0 + (av ? r : 0);
        asrc[i] = Abase + (size_t)grow * KTOT + fc16 * 8;
    }
    const __half* bsrc0 = Wb + (size_t)e * (size_t)KTOT * (FIRST ? HD2 : Hh)
                        + (size_t)(n0 + frow) * KTOT + fc16 * 8;
    uint32_t adst0 = sbase + frow * ROWPB + fc16 * 16;   // + i*32*ROWPB (imm)
    uint32_t bdst0 = adst0 + SA_BYTES;

    // ---- ldmatrix bases (add buf*STAGE + ks*32 + imm tile offsets in loop) ----
    // A im tile (rows wm*32+im*16): t0 m0-7@+0B t1 m8-15@+0B t2 m0-7@+16B t3 m8-15@+16B
    uint32_t aAdr = sbase + (uint32_t)((wm * 32 + ((lane >> 3) & 1) * 8 + (lane & 7)) * ROWPB
                                       + (lane >> 4) * 16);
    // B jp tile (rows wn*64+jp*16): t0 n0-7@+0B t1 n0-7@+16B t2 n8-15@+0B t3 n8-15@+16B
    uint32_t bAdr = sbase + SA_BYTES
                  + (uint32_t)((wn * 64 + (lane >> 4) * 8 + (lane & 7)) * ROWPB
                               + ((lane >> 3) & 1) * 16);

    float cf[2][8][4];
#pragma unroll
    for (int i = 0; i < 2; i++)
#pragma unroll
        for (int j = 0; j < 8; j++)
#pragma unroll
            for (int k = 0; k < 4; k++) cf[i][j][k] = 0.f;

    const int S = KTOT / TK;
#pragma unroll
    for (int s = 0; s < 2; s++) {
#pragma unroll
        for (int i = 0; i < 4; i++)
            CPA(adst0 + s * STAGE + i * (32 * ROWPB), asrc[i] + s * TK, anv[i]);
#pragma unroll
        for (int i = 0; i < 4; i++)
            CPA(bdst0 + s * STAGE + i * (32 * ROWPB), bsrc0 + (size_t)i * 32 * KTOT + s * TK, 16u);
        CPC();
    }

    int buf = 0;
    for (int s = 0; s < S; s++) {
        if (s + 1 < S) { CPW(1); } else { CPW(0); }
        __syncthreads();
        if (s + 2 < S) {
            int b2 = buf + 2; if (b2 >= NSTAGE) b2 -= NSTAGE;
            int k0 = (s + 2) * TK;
#pragma unroll
            for (int i = 0; i < 4; i++)
                CPA(adst0 + b2 * STAGE + i * (32 * ROWPB), asrc[i] + k0, anv[i]);
#pragma unroll
            for (int i = 0; i < 4; i++)
                CPA(bdst0 + b2 * STAGE + i * (32 * ROWPB), bsrc0 + (size_t)i * 32 * KTOT + k0, 16u);
            CPC();
        }
        uint32_t bufoff = (uint32_t)(buf * STAGE);
#pragma unroll
        for (int ks = 0; ks < 4; ks++) {       // 4 x k16 covers TK=64 halfs
            uint32_t koff = bufoff + ks * 32;  // 16 halfs = 32B per k-step
            uint32_t a[2][4];
            LDSM4(a[0][0], a[0][1], a[0][2], a[0][3], aAdr + koff);
            LDSM4(a[1][0], a[1][1], a[1][2], a[1][3], aAdr + koff + 16 * ROWPB);
            uint32_t bb[2][4];                 // double-buffered B fragments
            LDSM4(bb[0][0], bb[0][1], bb[0][2], bb[0][3], bAdr + koff);
#pragma unroll
            for (int jp = 0; jp < 4; jp++) {
                int cur = jp & 1;
                if (jp < 3) {
                    int nxt = cur ^ 1;
                    LDSM4(bb[nxt][0], bb[nxt][1], bb[nxt][2], bb[nxt][3],
                          bAdr + koff + (jp + 1) * (16 * ROWPB));
                }
                mma16(cf[0][2 * jp],     a[0], bb[cur][0], bb[cur][1]);
                mma16(cf[1][2 * jp],     a[1], bb[cur][0], bb[cur][1]);
                mma16(cf[0][2 * jp + 1], a[0], bb[cur][2], bb[cur][3]);
                mma16(cf[1][2 * jp + 1], a[1], bb[cur][2], bb[cur][3]);
            }
        }
        if (++buf == NSTAGE) buf = 0;
    }

    // ---------------- epilogue ----------------
    int base_slot = g_off[e] + m0;
    int colb = n0 + wn * 64 + 2 * lr;
#pragma unroll
    for (int im = 0; im < 2; im++) {
#pragma unroll
        for (int h = 0; h < 2; h++) {
            int r = wm * 32 + im * 16 + lq + h * 8;
            if (m0 + r >= cnt) continue;
            if (FIRST) {
                __half* orow = OutH + (size_t)(base_slot + r) * LDO + colb;
#pragma unroll
                for (int jn = 0; jn < 8; jn++) {
                    float v0 = gelu_f(cf[im][jn][2 * h]);
                    float v1 = gelu_f(cf[im][jn][2 * h + 1]);
                    *(__half2*)(orow + jn * 8) = __floats2half2_rn(v0, v1);
                }
            } else {
                float* orow = OutF + (size_t)(base_slot + r) * LDO + colb;
#pragma unroll
                for (int jn = 0; jn < 8; jn++)
                    *(float2*)(orow + jn * 8) = make_float2(cf[im][jn][2 * h],
                                                            cf[im][jn][2 * h + 1]);
            }
        }
    }
}

// ---------------------------------------------------------------------------
// Combine: out[t] = w0 * y[slot0] + w1 * y[slot1]
// ---------------------------------------------------------------------------
__global__ __launch_bounds__(256) void combine_kernel(float* __restrict__ out) {
    int t = blockIdx.x;
    int c = threadIdx.x;
    int4 mi = g_info[t];
    float2 gw = g_wts[t];
    size_t s0 = (size_t)(g_off[mi.x] + mi.y) * Hh + c * 4;
    size_t s1 = (size_t)(g_off[mi.z] + mi.w) * Hh + c * 4;
    float4 a = *(const float4*)(g_ybuf + s0);
    float4 b = *(const float4*)(g_ybuf + s1);
    float4 o;
    o.x = gw.x * a.x + gw.y * b.x;
    o.y = gw.x * a.y + gw.y * b.y;
    o.z = gw.x * a.z + gw.y * b.z;
    o.w = gw.x * a.w + gw.y * b.w;
    *(float4*)(out + (size_t)t * Hh + c * 4) = o;
}

// ---------------------------------------------------------------------------
extern "C" void kernel_launch(void* const* d_in, const int* in_sizes, int n_in,
                              void* d_out, int out_size) {
    const float* x  = (const float*)d_in[0];
    const float* rw = (const float*)d_in[1];
    const float* w1 = (const float*)d_in[2];
    const float* w2 = (const float*)d_in[3];
    float* out = (float*)d_out;

    void* cntp = nullptr; cudaGetSymbolAddress(&cntp, g_cnt);
    cudaMemsetAsync(cntp, 0, sizeof(int) * NE);

    void *xh, *w1h, *w2h, *hb, *yb;
    cudaGetSymbolAddress(&xh,  g_xh);
    cudaGetSymbolAddress(&w1h, g_w1h);
    cudaGetSymbolAddress(&w2h, g_w2h);
    cudaGetSymbolAddress(&hb,  g_hbuf);
    cudaGetSymbolAddress(&yb,  g_ybuf);

    // Launch order: memset(0) router(1) offsets(2) cvt(3) gemm1(4) gemm2(5) combine(6)
    // -> ncu -s 5 -c 1 captures gemm1.
    router_kernel<<<Tt / 8, 256>>>(x, rw);
    offsets_kernel<<<1, 32>>>();
    cvt_all_kernel<<<(N4X + 2 * N4W + 255) / 256, 256>>>((const float4*)x,
                                                         (const float4*)w1,
                                                         (const float4*)w2);

    cudaFuncSetAttribute(moe_gemm_kernel<Hh, true>,
                         cudaFuncAttributeMaxDynamicSharedMemorySize, SMEM_BYTES);
    cudaFuncSetAttribute(moe_gemm_kernel<HD2, false>,
                         cudaFuncAttributeMaxDynamicSharedMemorySize, SMEM_BYTES);

    dim3 g1(Tt / TM, HD2 / TN, NE);   // (64, 16, 8): GEMM1  N=2048, K=1024
    dim3 g2(Tt / TM, Hh  / TN, NE);   // (64,  8, 8): GEMM2  N=1024, K=2048
    moe_gemm_kernel<Hh,  true ><<<g1, 256, SMEM_BYTES>>>((const __half*)xh,
                                                         (const __half*)w1h,
                                                         (__half*)hb, nullptr);
    moe_gemm_kernel<HD2, false><<<g2, 256, SMEM_BYTES>>>((const __half*)hb,
                                                         (const __half*)w2h,
                                                         nullptr, (float*)yb);

    combine_kernel<<<Tt, 256>>>(out);
}